// round 3
// baseline (speedup 1.0000x reference)
#include <cuda_runtime.h>
#include <cstdint>
#include <math.h>

// ============================================================================
// BinaryLinear: y[8192,4096] = x[8192,4096] @ (aa*tanh(kk*W))^T + bias
// Plain-sm_103-compatible path: mma.sync.m16n8k8 tf32 register GEMM.
// CTA 128x128, 8 warps (2x4), warp tile 64x32, 3-stage cp.async, TK=32.
// Both operands pre-rounded to tf32 (cvt.rna) to kill HMMA truncation bias.
// ============================================================================

#define MDIM 8192
#define NDIM 4096
#define KDIM 4096

#define TM 128
#define TN 128
#define TK 32
#define NSTAGES 3
#define KITERS (KDIM / TK)          // 128

#define STAGE_FLOATS (2 * TM * TK)  // A + B = 8192 floats = 32KB
#define SMEM_BYTES (NSTAGES * STAGE_FLOATS * 4)   // 98304

// tanh(W) pre-rounded to tf32, persistent scratch
__device__ float g_wb[NDIM * KDIM];

// ---------------------------------------------------------------------------
__device__ __forceinline__ uint32_t smem_u32(const void* p) {
    uint32_t a;
    asm("{ .reg .u64 t; cvta.to.shared.u64 t, %1; cvt.u32.u64 %0, t; }" : "=r"(a) : "l"(p));
    return a;
}

__device__ __forceinline__ void cp_async16(uint32_t smem_dst, const void* gmem_src) {
    asm volatile("cp.async.cg.shared.global [%0], [%1], 16;" :: "r"(smem_dst), "l"(gmem_src));
}
#define CP_COMMIT() asm volatile("cp.async.commit_group;" ::: "memory")
#define CP_WAIT(n)  asm volatile("cp.async.wait_group %0;" :: "n"(n) : "memory")

__device__ __forceinline__ uint32_t f2tf32(float f) {
    uint32_t u;
    asm("cvt.rna.tf32.f32 %0, %1;" : "=r"(u) : "f"(f));
    return u;
}

__device__ __forceinline__ void mma_tf32(float d[4], const uint32_t a[4],
                                         const uint32_t b[2], const float c[4]) {
    asm volatile(
        "mma.sync.aligned.m16n8k8.row.col.f32.tf32.tf32.f32 "
        "{%0,%1,%2,%3}, {%4,%5,%6,%7}, {%8,%9}, {%10,%11,%12,%13};"
        : "=f"(d[0]), "=f"(d[1]), "=f"(d[2]), "=f"(d[3])
        : "r"(a[0]), "r"(a[1]), "r"(a[2]), "r"(a[3]),
          "r"(b[0]), "r"(b[1]),
          "f"(c[0]), "f"(c[1]), "f"(c[2]), "f"(c[3]));
}

// ---------------------------------------------------------------------------
// Kernel 1: wb = round_tf32(aa * tanh(kk * w))
// ---------------------------------------------------------------------------
__global__ void __launch_bounds__(256) prep_kernel(const float4* __restrict__ w,
                                                   const float* __restrict__ kk,
                                                   const float* __restrict__ aa) {
    int i = blockIdx.x * 256 + threadIdx.x;   // 16384 blocks * 256 = 4.19M float4
    float k = *kk, a = *aa;
    float4 v = w[i];
    uint4 r;
    r.x = f2tf32(a * tanhf(k * v.x));
    r.y = f2tf32(a * tanhf(k * v.y));
    r.z = f2tf32(a * tanhf(k * v.z));
    r.w = f2tf32(a * tanhf(k * v.w));
    reinterpret_cast<uint4*>(g_wb)[i] = r;
}

// ---------------------------------------------------------------------------
// Load one 32-K stage: A 128x32f + B 128x32f, 16B granules, XOR swizzle.
// Granule (row, c): float col range [4c,4c+4) stored at 16B slot (c ^ (row&7)).
// => element (row,col) lives at float index row*32 + (col ^ ((row&7)<<2)).
// ---------------------------------------------------------------------------
__device__ __forceinline__ void load_stage(const float* __restrict__ x,
                                           const float* __restrict__ wb,
                                           int m0, int n0, int k0,
                                           uint32_t sdst, int tid) {
#pragma unroll
    for (int i = 0; i < 4; i++) {                 // A: 1024 granules / 256 thr
        int g = tid + i * 256;
        int row = g >> 3, c = g & 7;
        cp_async16(sdst + row * 128 + ((c ^ (row & 7)) << 4),
                   x + (size_t)(m0 + row) * KDIM + k0 + c * 4);
    }
#pragma unroll
    for (int i = 0; i < 4; i++) {                 // B: 1024 granules
        int g = tid + i * 256;
        int row = g >> 3, c = g & 7;
        cp_async16(sdst + TM * TK * 4 + row * 128 + ((c ^ (row & 7)) << 4),
                   wb + (size_t)(n0 + row) * KDIM + k0 + c * 4);
    }
}

__device__ __forceinline__ int swz(int row, int col) {
    return row * 32 + (col ^ ((row & 7) << 2));
}

// ---------------------------------------------------------------------------
// Kernel 2: tf32 mma.sync GEMM
// ---------------------------------------------------------------------------
__global__ void __launch_bounds__(256, 2) gemm_kernel(const float* __restrict__ x,
                                                      const float* __restrict__ bias,
                                                      float* __restrict__ out) {
    extern __shared__ float smemf[];
    const uint32_t sbase = smem_u32(smemf);

    const int tid = threadIdx.x;
    const int wid = tid >> 5;
    const int lane = tid & 31;
    const int wm = wid >> 2;          // 0..1 -> 64-row slab
    const int wn = wid & 3;           // 0..3 -> 32-col slab
    const int lr = lane >> 2;         // 0..7
    const int lc = lane & 3;          // 0..3

    // grouped tile swizzle: 64 m-tiles x 32 n-tiles, GROUP_M = 8
    const int pid = blockIdx.x;
    const int group = pid >> 8;                   // / (8*32)
    const int rem = pid & 255;
    const int pm = (group << 3) + (rem & 7);
    const int pn = rem >> 3;
    const int m0 = pm * TM;
    const int n0 = pn * TN;

    float acc[4][4][4];
#pragma unroll
    for (int i = 0; i < 4; i++)
#pragma unroll
        for (int j = 0; j < 4; j++) {
            acc[i][j][0] = 0.f; acc[i][j][1] = 0.f;
            acc[i][j][2] = 0.f; acc[i][j][3] = 0.f;
        }

    // prologue: fill stages 0,1
#pragma unroll
    for (int s = 0; s < NSTAGES - 1; s++) {
        load_stage(x, g_wb, m0, n0, s * TK, sbase + s * STAGE_FLOATS * 4, tid);
        CP_COMMIT();
    }

    for (int it = 0; it < KITERS; ++it) {
        const int s = it % NSTAGES;
        CP_WAIT(1);              // stage `it` resident (one group per iter)
        __syncthreads();

        const float* aS = smemf + s * STAGE_FLOATS;           // A: 128x32
        const float* bS = aS + TM * TK;                       // B: 128x32

#pragma unroll
        for (int kk = 0; kk < 4; kk++) {
            const int c0 = kk * 8 + lc;
            uint32_t af[4][4];
#pragma unroll
            for (int ms = 0; ms < 4; ms++) {
                const int r0 = wm * 64 + ms * 16 + lr;
                af[ms][0] = f2tf32(aS[swz(r0,     c0)]);
                af[ms][1] = f2tf32(aS[swz(r0 + 8, c0)]);
                af[ms][2] = f2tf32(aS[swz(r0,     c0 + 4)]);
                af[ms][3] = f2tf32(aS[swz(r0 + 8, c0 + 4)]);
            }
            uint32_t bf[4][2];
#pragma unroll
            for (int ns = 0; ns < 4; ns++) {
                const int nr = wn * 32 + ns * 8 + lr;
                bf[ns][0] = __float_as_uint(bS[swz(nr, c0)]);      // wb pre-rounded
                bf[ns][1] = __float_as_uint(bS[swz(nr, c0 + 4)]);
            }
#pragma unroll
            for (int ms = 0; ms < 4; ms++)
#pragma unroll
                for (int ns = 0; ns < 4; ns++)
                    mma_tf32(acc[ms][ns], af[ms], bf[ns], acc[ms][ns]);
        }

        const int jt = it + NSTAGES - 1;          // prefetch stage jt
        if (jt < KITERS)
            load_stage(x, g_wb, m0, n0, jt * TK,
                       sbase + (jt % NSTAGES) * STAGE_FLOATS * 4, tid);
        CP_COMMIT();                              // always commit: CP_WAIT(1) stays valid
    }

    // epilogue: c0,c1 at (row, 2*lc), c2,c3 at (row+8, 2*lc)
#pragma unroll
    for (int ms = 0; ms < 4; ms++) {
        const int rg = m0 + wm * 64 + ms * 16 + lr;
        float* o0 = out + (size_t)rg * NDIM;
        float* o1 = out + (size_t)(rg + 8) * NDIM;
#pragma unroll
        for (int ns = 0; ns < 4; ns++) {
            const int cg = n0 + wn * 32 + ns * 8 + 2 * lc;
            const float2 bv = *reinterpret_cast<const float2*>(bias + cg);
            float2 v0, v1;
            v0.x = acc[ms][ns][0] + bv.x;  v0.y = acc[ms][ns][1] + bv.y;
            v1.x = acc[ms][ns][2] + bv.x;  v1.y = acc[ms][ns][3] + bv.y;
            *reinterpret_cast<float2*>(o0 + cg) = v0;
            *reinterpret_cast<float2*>(o1 + cg) = v1;
        }
    }
}

// ---------------------------------------------------------------------------
extern "C" void kernel_launch(void* const* d_in, const int* in_sizes, int n_in,
                              void* d_out, int out_size) {
    const float* x = (const float*)d_in[0];      // [4,2048,4096]
    const float* w = (const float*)d_in[1];      // [4096,4096]
    const float* bias = (const float*)d_in[2];   // [4096]
    const float* kk = (const float*)d_in[3];
    const float* aa = (const float*)d_in[4];
    float* out = (float*)d_out;                  // [4,2048,4096]

    prep_kernel<<<NDIM * KDIM / 1024, 256>>>((const float4*)w, kk, aa);

    cudaFuncSetAttribute(gemm_kernel, cudaFuncAttributeMaxDynamicSharedMemorySize, SMEM_BYTES);
    gemm_kernel<<<(MDIM / TM) * (NDIM / TN), 256, SMEM_BYTES>>>(x, bias, out);
}

// round 4
// speedup vs baseline: 1.3517x; 1.3517x over previous
#include <cuda_runtime.h>
#include <cstdint>
#include <math.h>

// ============================================================================
// BinaryLinear: y[8192,4096] = x[8192,4096] @ (aa*tanh(kk*W))^T + bias
// mma.sync.m16n8k8.tf32 register GEMM.
// CTA 128x256, 8 warps (2x4), warp tile 64x64, 3-stage cp.async, TK=32.
// Both operands pre-rounded to tf32 (cvt.rna) in prep kernels -> zero in-loop cvt.
// ============================================================================

#define MDIM 8192
#define NDIM 4096
#define KDIM 4096

#define TM 128
#define TN 256
#define TK 32
#define NSTAGES 3
#define KITERS (KDIM / TK)              // 128

#define A_STAGE_FLOATS (TM * TK)        // 4096
#define B_STAGE_FLOATS (TN * TK)        // 8192
#define STAGE_FLOATS (A_STAGE_FLOATS + B_STAGE_FLOATS)   // 12288 = 48KB
#define SMEM_BYTES (NSTAGES * STAGE_FLOATS * 4)          // 147456

// pre-rounded tf32 operands (persistent scratch)
__device__ float g_wb[NDIM * KDIM];     // aa*tanh(kk*W), tf32-rounded
__device__ float g_xb[MDIM * KDIM];     // x, tf32-rounded

// ---------------------------------------------------------------------------
__device__ __forceinline__ uint32_t smem_u32(const void* p) {
    uint32_t a;
    asm("{ .reg .u64 t; cvta.to.shared.u64 t, %1; cvt.u32.u64 %0, t; }" : "=r"(a) : "l"(p));
    return a;
}

__device__ __forceinline__ void cp_async16(uint32_t smem_dst, const void* gmem_src) {
    asm volatile("cp.async.cg.shared.global [%0], [%1], 16;" :: "r"(smem_dst), "l"(gmem_src));
}
#define CP_COMMIT() asm volatile("cp.async.commit_group;" ::: "memory")
#define CP_WAIT(n)  asm volatile("cp.async.wait_group %0;" :: "n"(n) : "memory")

__device__ __forceinline__ uint32_t f2tf32(float f) {
    uint32_t u;
    asm("cvt.rna.tf32.f32 %0, %1;" : "=r"(u) : "f"(f));
    return u;
}

__device__ __forceinline__ void mma_tf32(float d[4], const uint32_t a[4],
                                         const uint32_t b[2], const float c[4]) {
    asm volatile(
        "mma.sync.aligned.m16n8k8.row.col.f32.tf32.tf32.f32 "
        "{%0,%1,%2,%3}, {%4,%5,%6,%7}, {%8,%9}, {%10,%11,%12,%13};"
        : "=f"(d[0]), "=f"(d[1]), "=f"(d[2]), "=f"(d[3])
        : "r"(a[0]), "r"(a[1]), "r"(a[2]), "r"(a[3]),
          "r"(b[0]), "r"(b[1]),
          "f"(c[0]), "f"(c[1]), "f"(c[2]), "f"(c[3]));
}

// ---------------------------------------------------------------------------
// Prep kernels: tf32-round both operands once.
// ---------------------------------------------------------------------------
__global__ void __launch_bounds__(256) prep_w(const float4* __restrict__ w,
                                              const float* __restrict__ kk,
                                              const float* __restrict__ aa) {
    int i = blockIdx.x * 256 + threadIdx.x;
    float k = *kk, a = *aa;
    float4 v = w[i];
    uint4 r;
    r.x = f2tf32(a * tanhf(k * v.x));
    r.y = f2tf32(a * tanhf(k * v.y));
    r.z = f2tf32(a * tanhf(k * v.z));
    r.w = f2tf32(a * tanhf(k * v.w));
    reinterpret_cast<uint4*>(g_wb)[i] = r;
}

__global__ void __launch_bounds__(256) prep_x(const float4* __restrict__ x) {
    int i = blockIdx.x * 256 + threadIdx.x;
    float4 v = x[i];
    uint4 r;
    r.x = f2tf32(v.x);
    r.y = f2tf32(v.y);
    r.z = f2tf32(v.z);
    r.w = f2tf32(v.w);
    reinterpret_cast<uint4*>(g_xb)[i] = r;
}

// ---------------------------------------------------------------------------
// Load one 32-K stage: A 128x32f + B 256x32f, 16B granules, XOR swizzle.
// Element (row,col) lives at float index row*32 + (col ^ ((row&7)<<2)).
// ---------------------------------------------------------------------------
__device__ __forceinline__ void load_stage(const float* __restrict__ xb,
                                           const float* __restrict__ wb,
                                           int m0, int n0, int k0,
                                           uint32_t sdst, int tid) {
#pragma unroll
    for (int i = 0; i < 4; i++) {                 // A: 1024 granules / 256 thr
        int g = tid + i * 256;
        int row = g >> 3, c = g & 7;
        cp_async16(sdst + row * 128 + ((c ^ (row & 7)) << 4),
                   xb + (size_t)(m0 + row) * KDIM + k0 + c * 4);
    }
#pragma unroll
    for (int i = 0; i < 8; i++) {                 // B: 2048 granules
        int g = tid + i * 256;
        int row = g >> 3, c = g & 7;
        cp_async16(sdst + A_STAGE_FLOATS * 4 + row * 128 + ((c ^ (row & 7)) << 4),
                   wb + (size_t)(n0 + row) * KDIM + k0 + c * 4);
    }
}

__device__ __forceinline__ int swz(int row, int col) {
    return row * 32 + (col ^ ((row & 7) << 2));
}

// ---------------------------------------------------------------------------
// GEMM: warp tile 64x64 (ms=4 x ns=8 of m16n8), k-step 8, 4 k-steps per stage
// ---------------------------------------------------------------------------
__global__ void __launch_bounds__(256, 1) gemm_kernel(const float* __restrict__ bias,
                                                      float* __restrict__ out) {
    extern __shared__ float smemf[];
    const uint32_t sbase = smem_u32(smemf);

    const int tid = threadIdx.x;
    const int wid = tid >> 5;
    const int lane = tid & 31;
    const int wm = wid >> 2;          // 0..1 -> 64-row slab
    const int wn = wid & 3;           // 0..3 -> 64-col slab
    const int lr = lane >> 2;         // 0..7
    const int lc = lane & 3;          // 0..3

    // grouped tile swizzle: 64 m-tiles x 16 n-tiles, GROUP_M = 8
    const int pid = blockIdx.x;
    const int group = pid >> 7;                   // / (8*16)
    const int rem = pid & 127;
    const int pm = (group << 3) + (rem & 7);
    const int pn = rem >> 3;
    const int m0 = pm * TM;
    const int n0 = pn * TN;

    float acc[4][8][4];
#pragma unroll
    for (int i = 0; i < 4; i++)
#pragma unroll
        for (int j = 0; j < 8; j++) {
            acc[i][j][0] = 0.f; acc[i][j][1] = 0.f;
            acc[i][j][2] = 0.f; acc[i][j][3] = 0.f;
        }

    // prologue: fill stages 0,1
#pragma unroll
    for (int s = 0; s < NSTAGES - 1; s++) {
        load_stage(g_xb, g_wb, m0, n0, s * TK, sbase + s * STAGE_FLOATS * 4, tid);
        CP_COMMIT();
    }

    for (int it = 0; it < KITERS; ++it) {
        const int s = it % NSTAGES;
        CP_WAIT(1);              // stage `it` resident (one group per iter)
        __syncthreads();

        const float* aS = smemf + s * STAGE_FLOATS;   // A: 128x32
        const float* bS = aS + A_STAGE_FLOATS;        // B: 256x32

#pragma unroll
        for (int kq = 0; kq < 4; kq++) {
            const int c0 = kq * 8 + lc;
            uint32_t af[4][4];
#pragma unroll
            for (int ms = 0; ms < 4; ms++) {
                const int r0 = wm * 64 + ms * 16 + lr;
                af[ms][0] = __float_as_uint(aS[swz(r0,     c0)]);
                af[ms][1] = __float_as_uint(aS[swz(r0 + 8, c0)]);
                af[ms][2] = __float_as_uint(aS[swz(r0,     c0 + 4)]);
                af[ms][3] = __float_as_uint(aS[swz(r0 + 8, c0 + 4)]);
            }
            uint32_t bf[8][2];
#pragma unroll
            for (int ns = 0; ns < 8; ns++) {
                const int nr = wn * 64 + ns * 8 + lr;
                bf[ns][0] = __float_as_uint(bS[swz(nr, c0)]);
                bf[ns][1] = __float_as_uint(bS[swz(nr, c0 + 4)]);
            }
#pragma unroll
            for (int ms = 0; ms < 4; ms++)
#pragma unroll
                for (int ns = 0; ns < 8; ns++)
                    mma_tf32(acc[ms][ns], af[ms], bf[ns], acc[ms][ns]);
        }

        const int jt = it + NSTAGES - 1;          // prefetch stage jt
        if (jt < KITERS)
            load_stage(g_xb, g_wb, m0, n0, jt * TK,
                       sbase + (jt % NSTAGES) * STAGE_FLOATS * 4, tid);
        CP_COMMIT();                              // always commit: CP_WAIT(1) stays valid
    }

    // epilogue: c0,c1 at (row, 2*lc), c2,c3 at (row+8, 2*lc)
#pragma unroll
    for (int ms = 0; ms < 4; ms++) {
        const int rg = m0 + wm * 64 + ms * 16 + lr;
        float* o0 = out + (size_t)rg * NDIM;
        float* o1 = out + (size_t)(rg + 8) * NDIM;
#pragma unroll
        for (int ns = 0; ns < 8; ns++) {
            const int cg = n0 + wn * 64 + ns * 8 + 2 * lc;
            const float2 bv = *reinterpret_cast<const float2*>(bias + cg);
            float2 v0, v1;
            v0.x = acc[ms][ns][0] + bv.x;  v0.y = acc[ms][ns][1] + bv.y;
            v1.x = acc[ms][ns][2] + bv.x;  v1.y = acc[ms][ns][3] + bv.y;
            *reinterpret_cast<float2*>(o0 + cg) = v0;
            *reinterpret_cast<float2*>(o1 + cg) = v1;
        }
    }
}

// ---------------------------------------------------------------------------
extern "C" void kernel_launch(void* const* d_in, const int* in_sizes, int n_in,
                              void* d_out, int out_size) {
    const float* x = (const float*)d_in[0];      // [4,2048,4096]
    const float* w = (const float*)d_in[1];      // [4096,4096]
    const float* bias = (const float*)d_in[2];   // [4096]
    const float* kk = (const float*)d_in[3];
    const float* aa = (const float*)d_in[4];
    float* out = (float*)d_out;                  // [4,2048,4096]

    prep_w<<<NDIM * KDIM / 1024, 256>>>((const float4*)w, kk, aa);
    prep_x<<<MDIM * KDIM / 1024, 256>>>((const float4*)x);

    cudaFuncSetAttribute(gemm_kernel, cudaFuncAttributeMaxDynamicSharedMemorySize, SMEM_BYTES);
    gemm_kernel<<<(MDIM / TM) * (NDIM / TN), 256, SMEM_BYTES>>>(bias, out);
}